// round 2
// baseline (speedup 1.0000x reference)
#include <cuda_runtime.h>
#include <cuda_bf16.h>
#include <math.h>

#define N_NODES 19
#define N_T     4096
#define LATENT  512
#define HID     2048
#define N_EDGES 342
#define KT      64

// ---------------- scratch (__device__ globals; no allocs allowed) -----------
__device__ float g_x1[N_NODES * LATENT];
__device__ float g_t1[N_NODES * HID];
__device__ float g_h1[N_NODES * HID];
__device__ float g_x2[N_NODES * HID];
__device__ float g_h4[N_NODES * N_T];
__device__ float g_acc[N_NODES * N_T];     // split-K accumulator (in-place zeroed)
__device__ float g_v[LATENT];              // FC1 accumulator
__device__ int   g_adj[N_NODES * N_NODES]; // dense edge-count matrix [dst][src]

// ---------------- adjacency precompute + v zero -----------------------------
// Handles int64 OR int32 edge buffers (JAX x64 ambiguity) via runtime detect.
__global__ void adj_kernel(const void* __restrict__ eidx,
                           float* __restrict__ v) {
    __shared__ int cnt[N_NODES * N_NODES];
    __shared__ int s_i64;
    int t = threadIdx.x;
    if (t < N_NODES * N_NODES) cnt[t] = 0;
    if (t == 0) {
        const long long* e64 = (const long long*)eidx;
        int ok = 1;
        for (int i = 0; i < N_EDGES; ++i) {
            long long x = e64[i];
            if (x < 0 || x >= N_NODES) { ok = 0; break; }
        }
        s_i64 = ok;
    }
    __syncthreads();
    const long long* e64 = (const long long*)eidx;
    const int*       e32 = (const int*)eidx;
    for (int e = t; e < N_EDGES; e += blockDim.x) {
        int src, dst;
        if (s_i64) { src = (int)e64[e]; dst = (int)e64[N_EDGES + e]; }
        else       { src = e32[e];      dst = e32[N_EDGES + e]; }
        atomicAdd(&cnt[dst * N_NODES + src], 1);
    }
    __syncthreads();
    if (t < N_NODES * N_NODES) g_adj[t] = cnt[t];
    if (t < LATENT) v[t] = 0.0f;
}

// ---------------- GIN agg: out = h + adj @ h; optional zero of zbuf ---------
__global__ void agg_kernel(const float* __restrict__ h,
                           float* __restrict__ out, int C,
                           float* __restrict__ zbuf, int zn) {
    __shared__ float s_adj[N_NODES * N_NODES];
    for (int i = threadIdx.x; i < N_NODES * N_NODES; i += blockDim.x)
        s_adj[i] = (float)g_adj[i];
    __syncthreads();
    int total = N_NODES * C;
    for (int idx = blockIdx.x * blockDim.x + threadIdx.x; idx < total;
         idx += gridDim.x * blockDim.x) {
        int node = idx / C, c = idx - node * C;
        float a = h[idx];
#pragma unroll
        for (int s = 0; s < N_NODES; ++s) {
            float w = s_adj[node * N_NODES + s];
            a += w * h[s * C + c];
        }
        out[idx] = a;
    }
    if (zbuf) {
        for (int idx = blockIdx.x * blockDim.x + threadIdx.x; idx < zn;
             idx += gridDim.x * blockDim.x)
            zbuf[idx] = 0.0f;
    }
}

// ---------------- split-K GEMM partial: Cacc += A[19,K] @ W[K,N] ------------
// 128 threads x 2 cols = 256-col tile; grid.y slabs of kchunk.
// A staged into smem pre-duplicated {a,a}; inner loop: 8-deep W preload
// (MLP=8) + paired LDS.128 + fma.rn.f32x2.
__global__ __launch_bounds__(128) void gemm_partial(
        const float* __restrict__ A, const float* __restrict__ W,
        float* __restrict__ Cacc, int K, int N, int kchunk) {
    __shared__ __align__(16) unsigned long long sA[N_NODES][KT];

    int col  = blockIdx.x * 256 + threadIdx.x * 2;
    int kbeg = blockIdx.y * kchunk;

    unsigned long long acc[N_NODES];
#pragma unroll
    for (int r = 0; r < N_NODES; ++r) acc[r] = 0ull;

    for (int k0 = kbeg; k0 < kbeg + kchunk; k0 += KT) {
        for (int i = threadIdx.x; i < N_NODES * KT; i += 128) {
            int r = i >> 6, k = i & (KT - 1);
            float a = A[r * K + k0 + k];
            unsigned long long p;
            asm("mov.b64 %0, {%1, %1};" : "=l"(p) : "f"(a));
            sA[r][k] = p;
        }
        __syncthreads();

        const float* Wp = W + (size_t)k0 * N + col;
#pragma unroll 1
        for (int kk = 0; kk < KT; kk += 8) {
            unsigned long long w[8];
#pragma unroll
            for (int j = 0; j < 8; ++j)
                w[j] = *reinterpret_cast<const unsigned long long*>(
                           Wp + (size_t)(kk + j) * N);
#pragma unroll
            for (int r = 0; r < N_NODES; ++r) {
#pragma unroll
                for (int jj = 0; jj < 8; jj += 2) {
                    ulonglong2 a2 = *reinterpret_cast<const ulonglong2*>(
                                        &sA[r][kk + jj]);
                    asm("fma.rn.f32x2 %0, %1, %2, %0;"
                        : "+l"(acc[r]) : "l"(a2.x), "l"(w[jj]));
                    asm("fma.rn.f32x2 %0, %1, %2, %0;"
                        : "+l"(acc[r]) : "l"(a2.y), "l"(w[jj + 1]));
                }
            }
        }
        __syncthreads();
    }

#pragma unroll
    for (int r = 0; r < N_NODES; ++r) {
        float2 p = *reinterpret_cast<float2*>(&acc[r]);
        atomicAdd(&Cacc[r * N + col],     p.x);
        atomicAdd(&Cacc[r * N + col + 1], p.y);
    }
}

// ---------------- epilogue: out = [relu](acc+bias); zero acc[0..zn) ---------
__global__ void epi_kernel(float* __restrict__ acc,
                           const float* __restrict__ bias,
                           float* __restrict__ out,
                           int nmask, int total, int zn, int do_relu) {
    int n4 = zn >> 2;
    for (int q = blockIdx.x * blockDim.x + threadIdx.x; q < n4;
         q += gridDim.x * blockDim.x) {
        int i = q << 2;
        if (i < total) {
            float4 a = *reinterpret_cast<float4*>(&acc[i]);
            const float4 b = *reinterpret_cast<const float4*>(&bias[i & nmask]);
            float4 r;
            r.x = a.x + b.x; r.y = a.y + b.y;
            r.z = a.z + b.z; r.w = a.w + b.w;
            if (do_relu) {
                r.x = fmaxf(r.x, 0.0f); r.y = fmaxf(r.y, 0.0f);
                r.z = fmaxf(r.z, 0.0f); r.w = fmaxf(r.w, 0.0f);
            }
            *reinterpret_cast<float4*>(&out[i]) = r;
        }
        *reinterpret_cast<float4*>(&acc[i]) = make_float4(0.f, 0.f, 0.f, 0.f);
    }
}

// ---------------- FC1 fused: flat = acc + b2b (also written to out1);
//                  v[512] += flat @ Wc1 -----------------------------------
__global__ __launch_bounds__(128) void fc1_kernel(
        const float* __restrict__ acc, const float* __restrict__ b2b,
        const float* __restrict__ Wc1, float* __restrict__ v,
        float* __restrict__ out1, int rows_per) {
    const int ROWS = N_NODES * N_T;
    int t = threadIdx.x;                       // cols 4t..4t+3
    int r0 = blockIdx.x * rows_per;
    int r1 = min(r0 + rows_per, ROWS);
    float4 s = make_float4(0.f, 0.f, 0.f, 0.f);
#pragma unroll 4
    for (int i = r0; i < r1; ++i) {
        float f = acc[i] + b2b[i & (N_T - 1)];
        if (t == (i & 127)) out1[i] = f;
        float4 w = *reinterpret_cast<const float4*>(
                       &Wc1[(size_t)i * LATENT + 4 * t]);
        s.x += f * w.x; s.y += f * w.y; s.z += f * w.z; s.w += f * w.w;
    }
    atomicAdd(&v[4 * t],     s.x);
    atomicAdd(&v[4 * t + 1], s.y);
    atomicAdd(&v[4 * t + 2], s.z);
    atomicAdd(&v[4 * t + 3], s.w);
}

// ---------------- FC2 + sigmoid ---------------------------------------------
__global__ void fc2_kernel(const float* __restrict__ v,
                           const float* __restrict__ bc1,
                           const float* __restrict__ Wc2,
                           const float* __restrict__ bc2,
                           float* __restrict__ out) {
    __shared__ float red[LATENT];
    int j = threadIdx.x;
    red[j] = (v[j] + bc1[j]) * Wc2[j];
    __syncthreads();
    for (int s = LATENT / 2; s > 0; s >>= 1) {
        if (j < s) red[j] += red[j + s];
        __syncthreads();
    }
    if (j == 0) out[0] = 1.0f / (1.0f + expf(-(red[0] + bc2[0])));
}

// ---------------- launch ----------------------------------------------------
extern "C" void kernel_launch(void* const* d_in, const int* in_sizes, int n_in,
                              void* d_out, int out_size) {
    const float* z    = (const float*)d_in[0];
    const void*  eidx = d_in[1];
    const float* W1a  = (const float*)d_in[2];
    const float* b1a  = (const float*)d_in[3];
    const float* W1b  = (const float*)d_in[4];
    const float* b1b  = (const float*)d_in[5];
    const float* W2a  = (const float*)d_in[6];
    const float* b2a  = (const float*)d_in[7];
    const float* W2b  = (const float*)d_in[8];
    const float* b2b  = (const float*)d_in[9];
    const float* Wc1  = (const float*)d_in[10];
    const float* bc1  = (const float*)d_in[11];
    const float* Wc2  = (const float*)d_in[12];
    const float* bc2  = (const float*)d_in[13];
    float* out = (float*)d_out;

    float *x1, *t1, *h1, *x2, *h4, *acc, *v;
    cudaGetSymbolAddress((void**)&x1,  g_x1);
    cudaGetSymbolAddress((void**)&t1,  g_t1);
    cudaGetSymbolAddress((void**)&h1,  g_h1);
    cudaGetSymbolAddress((void**)&x2,  g_x2);
    cudaGetSymbolAddress((void**)&h4,  g_h4);
    cudaGetSymbolAddress((void**)&acc, g_acc);
    cudaGetSymbolAddress((void**)&v,   g_v);

    const int nHID = N_NODES * HID;   // 38912
    const int nNT  = N_NODES * N_T;   // 77824

    adj_kernel<<<1, 512>>>(eidx, v);

    // ---- GIN layer 1 ----
    agg_kernel<<<76, 256>>>(z, x1, LATENT, acc, nHID);           // + zero acc
    gemm_partial<<<dim3(HID / 256, 4), 128>>>(x1, W1a, acc, LATENT, HID, 128);
    epi_kernel<<<76, 256>>>(acc, b1a, t1, HID - 1, nHID, nHID, 1);
    gemm_partial<<<dim3(HID / 256, 16), 128>>>(t1, W1b, acc, HID, HID, 128);
    epi_kernel<<<76, 256>>>(acc, b1b, h1, HID - 1, nHID, nNT, 1); // zero to nNT

    // ---- GIN layer 2 ----
    agg_kernel<<<152, 256>>>(h1, x2, HID, nullptr, 0);
    gemm_partial<<<dim3(N_T / 256, 16), 128>>>(x2, W2a, acc, HID, N_T, 128);
    epi_kernel<<<76, 256>>>(acc, b2a, h4, N_T - 1, nNT, nNT, 1);
    gemm_partial<<<dim3(N_T / 256, 32), 128>>>(h4, W2b, acc, N_T, N_T, 128);

    // ---- classifier (epilogue fused into FC1) ----
    fc1_kernel<<<590, 128>>>(acc, b2b, Wc1, v, out + 1, 132);
    fc2_kernel<<<1, 512>>>(v, bc1, Wc2, bc2, out);
}

// round 5
// speedup vs baseline: 1.7077x; 1.7077x over previous
#include <cuda_runtime.h>
#include <cuda_bf16.h>
#include <math.h>

#define N_NODES 19
#define N_T     4096
#define LATENT  512
#define HID     2048
#define N_EDGES 342

// ---------------- scratch (__device__ globals; no allocs allowed) -----------
__device__ float g_accA[N_NODES * N_T];
__device__ float g_accB[N_NODES * N_T];
__device__ float g_accC[N_NODES * N_T];
__device__ float g_v[LATENT];
__device__ float g_adjf[N_NODES * N_NODES]; // dense edge-count matrix [dst][src]

// ---------------- K0: adjacency + zero all accumulators ---------------------
// Handles int64 OR int32 edge buffers (JAX x64 ambiguity) via runtime detect.
__global__ void init_kernel(const void* __restrict__ eidx,
                            float* __restrict__ accA,
                            float* __restrict__ accB,
                            float* __restrict__ accC,
                            float* __restrict__ v) {
    int t = threadIdx.x;
    if (blockIdx.x == 0) {
        __shared__ int cnt[N_NODES * N_NODES];
        __shared__ int s_i64;
        // BUGFIX (R4): N_NODES^2 = 361 > blockDim = 256. The old
        // `if (t < 361)` guards left cnt[256:361) uninitialized and
        // g_adjf[256:361) unwritten -> corrupted adjacency for nodes >= 13.
        for (int i = t; i < N_NODES * N_NODES; i += blockDim.x) cnt[i] = 0;
        if (t == 0) {
            const long long* e64 = (const long long*)eidx;
            int ok = 1;
            for (int i = 0; i < N_EDGES; ++i) {
                long long x = e64[i];
                if (x < 0 || x >= N_NODES) { ok = 0; break; }
            }
            s_i64 = ok;
        }
        __syncthreads();
        const long long* e64 = (const long long*)eidx;
        const int*       e32 = (const int*)eidx;
        for (int e = t; e < N_EDGES; e += blockDim.x) {
            int src, dst;
            if (s_i64) { src = (int)e64[e]; dst = (int)e64[N_EDGES + e]; }
            else       { src = e32[e];      dst = e32[N_EDGES + e]; }
            atomicAdd(&cnt[dst * N_NODES + src], 1);
        }
        __syncthreads();
        for (int i = t; i < N_NODES * N_NODES; i += blockDim.x)
            g_adjf[i] = (float)cnt[i];
        for (int i = t; i < LATENT; i += blockDim.x) v[i] = 0.0f;
    }
    // all blocks: zero the three accumulators (float4)
    const int n4 = (N_NODES * N_T) >> 2;
    float4 zz = make_float4(0.f, 0.f, 0.f, 0.f);
    for (int q = blockIdx.x * blockDim.x + t; q < n4;
         q += gridDim.x * blockDim.x) {
        reinterpret_cast<float4*>(accA)[q] = zz;
        reinterpret_cast<float4*>(accB)[q] = zz;
        reinterpret_cast<float4*>(accC)[q] = zz;
    }
}

// ---------------- fused split-K GEMM ----------------------------------------
// Cacc += stage(Ain)[19,K] @ W[K,N], 128 threads x 2 cols = 256-col tile.
// MODE 0: stage = agg(Ain)                 (GIN agg on raw input)
// MODE 1: stage = relu(Ain + bias)         (epilogue of previous GEMM)
// MODE 2: stage = agg(relu(Ain + bias))
// W is software-pipelined 8 deep (prefetch next chunk before computing).
// Optionally zeroes zbuf[0..zn) for a later kernel's accumulator.
template<int KT, int MODE>
__global__ __launch_bounds__(128, 4) void gemm_fused(
        const float* __restrict__ Ain, const float* __restrict__ bias,
        const float* __restrict__ W, float* __restrict__ Cacc,
        float* __restrict__ zbuf, int zn,
        int K, int N, int kchunk) {
    __shared__ float sRaw[N_NODES][KT];
    __shared__ __align__(16) unsigned long long sA[N_NODES][KT];
    __shared__ float s_adj[N_NODES * N_NODES];

    int tid = threadIdx.x;

    // lazy zeroing for a future accumulator
    if (zbuf) {
        int n4 = zn >> 2;
        float4 zz = make_float4(0.f, 0.f, 0.f, 0.f);
        for (int q = (blockIdx.y * gridDim.x + blockIdx.x) * 128 + tid;
             q < n4; q += gridDim.x * gridDim.y * 128)
            reinterpret_cast<float4*>(zbuf)[q] = zz;
    }
    if (MODE == 0 || MODE == 2) {
        for (int i = tid; i < N_NODES * N_NODES; i += 128)
            s_adj[i] = g_adjf[i];
    }

    int col  = blockIdx.x * 256 + tid * 2;
    int kbeg = blockIdx.y * kchunk;
    int kend = kbeg + kchunk;

    unsigned long long acc[N_NODES];
#pragma unroll
    for (int r = 0; r < N_NODES; ++r) acc[r] = 0ull;

    // --- W prefetch pipeline (8 deep) ---
    unsigned long long pf[8];
    {
        const float* Wn = W + (size_t)kbeg * N + col;
#pragma unroll
        for (int j = 0; j < 8; ++j)
            pf[j] = *reinterpret_cast<const unsigned long long*>(
                        Wn + (size_t)j * N);
    }
    int kabs = kbeg;

    for (int k0 = kbeg; k0 < kend; k0 += KT) {
        // ---- stage A slab (fused epilogue/agg) ----
        for (int i = tid; i < N_NODES * KT; i += 128) {
            int r = i / KT, k = i - r * KT;
            float a = Ain[r * K + k0 + k];
            if (MODE >= 1) a = fmaxf(a + bias[k0 + k], 0.0f);
            if (MODE == 1) {
                unsigned long long p;
                asm("mov.b64 %0, {%1, %1};" : "=l"(p) : "f"(a));
                sA[r][k] = p;
            } else {
                sRaw[r][k] = a;
            }
        }
        __syncthreads();
        if (MODE == 0 || MODE == 2) {
            for (int i = tid; i < N_NODES * KT; i += 128) {
                int r = i / KT, k = i - r * KT;
                float a = sRaw[r][k];
#pragma unroll
                for (int s = 0; s < N_NODES; ++s)
                    a += s_adj[r * N_NODES + s] * sRaw[s][k];
                unsigned long long p;
                asm("mov.b64 %0, {%1, %1};" : "=l"(p) : "f"(a));
                sA[r][k] = p;
            }
            __syncthreads();
        }

        // ---- main loop: consume pf, prefetch next chunk, compute ----
#pragma unroll 1
        for (int kk = 0; kk < KT; kk += 8) {
            unsigned long long w[8];
#pragma unroll
            for (int j = 0; j < 8; ++j) w[j] = pf[j];
            kabs += 8;
            if (kabs < kend) {
                const float* Wn = W + (size_t)kabs * N + col;
#pragma unroll
                for (int j = 0; j < 8; ++j)
                    pf[j] = *reinterpret_cast<const unsigned long long*>(
                                Wn + (size_t)j * N);
            }
#pragma unroll
            for (int r = 0; r < N_NODES; ++r) {
#pragma unroll
                for (int jj = 0; jj < 8; jj += 2) {
                    ulonglong2 a2 = *reinterpret_cast<const ulonglong2*>(
                                        &sA[r][kk + jj]);
                    asm("fma.rn.f32x2 %0, %1, %2, %0;"
                        : "+l"(acc[r]) : "l"(a2.x), "l"(w[jj]));
                    asm("fma.rn.f32x2 %0, %1, %2, %0;"
                        : "+l"(acc[r]) : "l"(a2.y), "l"(w[jj + 1]));
                }
            }
        }
        __syncthreads();
    }

#pragma unroll
    for (int r = 0; r < N_NODES; ++r) {
        float2 p = *reinterpret_cast<float2*>(&acc[r]);
        atomicAdd(&Cacc[r * N + col],     p.x);
        atomicAdd(&Cacc[r * N + col + 1], p.y);
    }
}

// ---------------- FC1 fused: flat = acc + b2b (also written to out1);
//                  v[512] += flat @ Wc1 --------------------------------------
__global__ __launch_bounds__(128) void fc1_kernel(
        const float* __restrict__ acc, const float* __restrict__ b2b,
        const float* __restrict__ Wc1, float* __restrict__ v,
        float* __restrict__ out1, int rows_per) {
    const int ROWS = N_NODES * N_T;
    int t = threadIdx.x;                       // cols 4t..4t+3
    int r0 = blockIdx.x * rows_per;
    int r1 = min(r0 + rows_per, ROWS);
    float4 s = make_float4(0.f, 0.f, 0.f, 0.f);
#pragma unroll 4
    for (int i = r0; i < r1; ++i) {
        float f = acc[i] + b2b[i & (N_T - 1)];
        if (t == (i & 127)) out1[i] = f;
        float4 w = *reinterpret_cast<const float4*>(
                       &Wc1[(size_t)i * LATENT + 4 * t]);
        s.x += f * w.x; s.y += f * w.y; s.z += f * w.z; s.w += f * w.w;
    }
    atomicAdd(&v[4 * t],     s.x);
    atomicAdd(&v[4 * t + 1], s.y);
    atomicAdd(&v[4 * t + 2], s.z);
    atomicAdd(&v[4 * t + 3], s.w);
}

// ---------------- FC2 + sigmoid ---------------------------------------------
__global__ void fc2_kernel(const float* __restrict__ v,
                           const float* __restrict__ bc1,
                           const float* __restrict__ Wc2,
                           const float* __restrict__ bc2,
                           float* __restrict__ out) {
    __shared__ float red[LATENT];
    int j = threadIdx.x;
    red[j] = (v[j] + bc1[j]) * Wc2[j];
    __syncthreads();
    for (int s = LATENT / 2; s > 0; s >>= 1) {
        if (j < s) red[j] += red[j + s];
        __syncthreads();
    }
    if (j == 0) out[0] = 1.0f / (1.0f + expf(-(red[0] + bc2[0])));
}

// ---------------- launch ----------------------------------------------------
extern "C" void kernel_launch(void* const* d_in, const int* in_sizes, int n_in,
                              void* d_out, int out_size) {
    const float* z    = (const float*)d_in[0];
    const void*  eidx = d_in[1];
    const float* W1a  = (const float*)d_in[2];
    const float* b1a  = (const float*)d_in[3];
    const float* W1b  = (const float*)d_in[4];
    const float* b1b  = (const float*)d_in[5];
    const float* W2a  = (const float*)d_in[6];
    const float* b2a  = (const float*)d_in[7];
    const float* W2b  = (const float*)d_in[8];
    const float* b2b  = (const float*)d_in[9];
    const float* Wc1  = (const float*)d_in[10];
    const float* bc1  = (const float*)d_in[11];
    const float* Wc2  = (const float*)d_in[12];
    const float* bc2  = (const float*)d_in[13];
    float* out = (float*)d_out;

    float *accA, *accB, *accC, *v;
    cudaGetSymbolAddress((void**)&accA, g_accA);
    cudaGetSymbolAddress((void**)&accB, g_accB);
    cudaGetSymbolAddress((void**)&accC, g_accC);
    cudaGetSymbolAddress((void**)&v,    g_v);

    const int nNT = N_NODES * N_T;   // 77824

    // K0: adjacency + zero accA/accB/accC/v
    init_kernel<<<148, 256>>>(eidx, accA, accB, accC, v);

    // g1a: accA = agg(z) @ W1a          [19,512]x[512,2048]
    gemm_fused<32, 0><<<dim3(HID / 256, LATENT / 32), 128>>>(
        z, nullptr, W1a, accA, nullptr, 0, LATENT, HID, 32);

    // g1b: accB = relu(accA+b1a) @ W1b  [19,2048]x[2048,2048]
    gemm_fused<64, 1><<<dim3(HID / 256, HID / 64), 128>>>(
        accA, b1a, W1b, accB, nullptr, 0, HID, HID, 64);

    // g2a: accC = agg(relu(accB+b1b)) @ W2a   [19,2048]x[2048,4096]
    //      (also lazily zeroes accA for g2b)
    gemm_fused<64, 2><<<dim3(N_T / 256, HID / 128), 128>>>(
        accB, b1b, W2a, accC, accA, nNT, HID, N_T, 128);

    // g2b: accA = relu(accC+b2a) @ W2b  [19,4096]x[4096,4096]
    gemm_fused<64, 1><<<dim3(N_T / 256, N_T / 128), 128>>>(
        accC, b2a, W2b, accA, nullptr, 0, N_T, N_T, 128);

    // classifier: epilogue (+b2b, write out[1:]) fused into FC1
    fc1_kernel<<<592, 128>>>(accA, b2b, Wc1, v, out + 1, 132);
    fc2_kernel<<<1, 512>>>(v, bc1, Wc2, bc2, out);
}

// round 6
// speedup vs baseline: 1.8235x; 1.0678x over previous
#include <cuda_runtime.h>
#include <cuda_bf16.h>
#include <math.h>

#define N_NODES 19
#define N_T     4096
#define LATENT  512
#define HID     2048
#define N_EDGES 342

// ---------------- scratch (__device__ globals; no allocs allowed) -----------
__device__ float g_accA[N_NODES * N_T];
__device__ float g_accB[N_NODES * N_T];
__device__ float g_accC[N_NODES * N_T];
__device__ float g_v[LATENT];
__device__ float g_adjf[N_NODES * N_NODES]; // dense edge-count matrix [dst][src]

// ---------------- K0: adjacency + zero all accumulators ---------------------
// Handles int64 OR int32 edge buffers (JAX x64 ambiguity) via runtime detect.
__global__ void init_kernel(const void* __restrict__ eidx,
                            float* __restrict__ accA,
                            float* __restrict__ accB,
                            float* __restrict__ accC,
                            float* __restrict__ v) {
    int t = threadIdx.x;
    if (blockIdx.x == 0) {
        __shared__ int cnt[N_NODES * N_NODES];
        __shared__ int s_i64;
        for (int i = t; i < N_NODES * N_NODES; i += blockDim.x) cnt[i] = 0;
        if (t == 0) {
            const long long* e64 = (const long long*)eidx;
            int ok = 1;
            for (int i = 0; i < N_EDGES; ++i) {
                long long x = e64[i];
                if (x < 0 || x >= N_NODES) { ok = 0; break; }
            }
            s_i64 = ok;
        }
        __syncthreads();
        const long long* e64 = (const long long*)eidx;
        const int*       e32 = (const int*)eidx;
        for (int e = t; e < N_EDGES; e += blockDim.x) {
            int src, dst;
            if (s_i64) { src = (int)e64[e]; dst = (int)e64[N_EDGES + e]; }
            else       { src = e32[e];      dst = e32[N_EDGES + e]; }
            atomicAdd(&cnt[dst * N_NODES + src], 1);
        }
        __syncthreads();
        for (int i = t; i < N_NODES * N_NODES; i += blockDim.x)
            g_adjf[i] = (float)cnt[i];
        for (int i = t; i < LATENT; i += blockDim.x) v[i] = 0.0f;
    }
    // all blocks: zero the three accumulators (float4)
    const int n4 = (N_NODES * N_T) >> 2;
    float4 zz = make_float4(0.f, 0.f, 0.f, 0.f);
    for (int q = blockIdx.x * blockDim.x + t; q < n4;
         q += gridDim.x * blockDim.x) {
        reinterpret_cast<float4*>(accA)[q] = zz;
        reinterpret_cast<float4*>(accB)[q] = zz;
        reinterpret_cast<float4*>(accC)[q] = zz;
    }
}

// ---------------- fused split-K GEMM ----------------------------------------
// Cacc += stage(Ain)[19,K] @ W[K,N].  256 threads x 2 cols = 512-col tile.
// MODE 0: stage = agg(Ain)
// MODE 1: stage = relu(Ain + bias)
// MODE 2: stage = agg(relu(Ain + bias))
// W software-pipelined 8 deep; 2 blocks/SM guaranteed (launch_bounds 256,2).
template<int KT, int MODE>
__global__ __launch_bounds__(256, 2) void gemm_fused(
        const float* __restrict__ Ain, const float* __restrict__ bias,
        const float* __restrict__ W, float* __restrict__ Cacc,
        float* __restrict__ zbuf, int zn,
        int K, int N, int kchunk) {
    __shared__ float sRaw[N_NODES][KT];
    __shared__ __align__(16) unsigned long long sA[N_NODES][KT];
    __shared__ float s_adj[N_NODES * N_NODES];

    int tid = threadIdx.x;

    // lazy zeroing for a future accumulator
    if (zbuf) {
        int n4 = zn >> 2;
        float4 zz = make_float4(0.f, 0.f, 0.f, 0.f);
        for (int q = (blockIdx.y * gridDim.x + blockIdx.x) * 256 + tid;
             q < n4; q += gridDim.x * gridDim.y * 256)
            reinterpret_cast<float4*>(zbuf)[q] = zz;
    }
    if (MODE == 0 || MODE == 2) {
        for (int i = tid; i < N_NODES * N_NODES; i += 256)
            s_adj[i] = g_adjf[i];
    }

    int col  = blockIdx.x * 512 + tid * 2;
    int kbeg = blockIdx.y * kchunk;
    int kend = kbeg + kchunk;

    unsigned long long acc[N_NODES];
#pragma unroll
    for (int r = 0; r < N_NODES; ++r) acc[r] = 0ull;

    // --- W prefetch pipeline (8 deep) ---
    unsigned long long pf[8];
    {
        const float* Wn = W + (size_t)kbeg * N + col;
#pragma unroll
        for (int j = 0; j < 8; ++j)
            pf[j] = *reinterpret_cast<const unsigned long long*>(
                        Wn + (size_t)j * N);
    }
    int kabs = kbeg;

    for (int k0 = kbeg; k0 < kend; k0 += KT) {
        // ---- stage A slab (fused epilogue/agg) ----
        for (int i = tid; i < N_NODES * KT; i += 256) {
            int r = i / KT, k = i - r * KT;
            float a = Ain[r * K + k0 + k];
            if (MODE >= 1) a = fmaxf(a + bias[k0 + k], 0.0f);
            if (MODE == 1) {
                unsigned long long p;
                asm("mov.b64 %0, {%1, %1};" : "=l"(p) : "f"(a));
                sA[r][k] = p;
            } else {
                sRaw[r][k] = a;
            }
        }
        __syncthreads();
        if (MODE == 0 || MODE == 2) {
            for (int i = tid; i < N_NODES * KT; i += 256) {
                int r = i / KT, k = i - r * KT;
                float a = sRaw[r][k];
#pragma unroll
                for (int s = 0; s < N_NODES; ++s)
                    a += s_adj[r * N_NODES + s] * sRaw[s][k];
                unsigned long long p;
                asm("mov.b64 %0, {%1, %1};" : "=l"(p) : "f"(a));
                sA[r][k] = p;
            }
            __syncthreads();
        }

        // ---- main loop: consume pf, prefetch next chunk, compute ----
#pragma unroll 1
        for (int kk = 0; kk < KT; kk += 8) {
            unsigned long long w[8];
#pragma unroll
            for (int j = 0; j < 8; ++j) w[j] = pf[j];
            kabs += 8;
            if (kabs < kend) {
                const float* Wn = W + (size_t)kabs * N + col;
#pragma unroll
                for (int j = 0; j < 8; ++j)
                    pf[j] = *reinterpret_cast<const unsigned long long*>(
                                Wn + (size_t)j * N);
            }
#pragma unroll
            for (int r = 0; r < N_NODES; ++r) {
#pragma unroll
                for (int jj = 0; jj < 8; jj += 2) {
                    ulonglong2 a2 = *reinterpret_cast<const ulonglong2*>(
                                        &sA[r][kk + jj]);
                    asm("fma.rn.f32x2 %0, %1, %2, %0;"
                        : "+l"(acc[r]) : "l"(a2.x), "l"(w[jj]));
                    asm("fma.rn.f32x2 %0, %1, %2, %0;"
                        : "+l"(acc[r]) : "l"(a2.y), "l"(w[jj + 1]));
                }
            }
        }
        __syncthreads();
    }

#pragma unroll
    for (int r = 0; r < N_NODES; ++r) {
        float2 p = *reinterpret_cast<float2*>(&acc[r]);
        atomicAdd(&Cacc[r * N + col],     p.x);
        atomicAdd(&Cacc[r * N + col + 1], p.y);
    }
}

// ---------------- FC1 fused: flat = acc + b2b (also written to out1);
//                  v[512] += flat @ Wc1 --------------------------------------
__global__ __launch_bounds__(128) void fc1_kernel(
        const float* __restrict__ acc, const float* __restrict__ b2b,
        const float* __restrict__ Wc1, float* __restrict__ v,
        float* __restrict__ out1, int rows_per) {
    const int ROWS = N_NODES * N_T;
    int t = threadIdx.x;                       // cols 4t..4t+3
    int r0 = blockIdx.x * rows_per;
    int r1 = min(r0 + rows_per, ROWS);
    float4 s = make_float4(0.f, 0.f, 0.f, 0.f);
    int i = r0;
    for (; i + 8 <= r1; i += 8) {
        float f[8];
        float4 w[8];
#pragma unroll
        for (int u = 0; u < 8; ++u) {
            f[u] = acc[i + u] + b2b[(i + u) & (N_T - 1)];
            w[u] = *reinterpret_cast<const float4*>(
                       &Wc1[(size_t)(i + u) * LATENT + 4 * t]);
        }
#pragma unroll
        for (int u = 0; u < 8; ++u) {
            if (t == ((i + u) & 127)) out1[i + u] = f[u];
            s.x += f[u] * w[u].x; s.y += f[u] * w[u].y;
            s.z += f[u] * w[u].z; s.w += f[u] * w[u].w;
        }
    }
    for (; i < r1; ++i) {
        float f = acc[i] + b2b[i & (N_T - 1)];
        if (t == (i & 127)) out1[i] = f;
        float4 w = *reinterpret_cast<const float4*>(
                       &Wc1[(size_t)i * LATENT + 4 * t]);
        s.x += f * w.x; s.y += f * w.y; s.z += f * w.z; s.w += f * w.w;
    }
    atomicAdd(&v[4 * t],     s.x);
    atomicAdd(&v[4 * t + 1], s.y);
    atomicAdd(&v[4 * t + 2], s.z);
    atomicAdd(&v[4 * t + 3], s.w);
}

// ---------------- FC2 + sigmoid ---------------------------------------------
__global__ void fc2_kernel(const float* __restrict__ v,
                           const float* __restrict__ bc1,
                           const float* __restrict__ Wc2,
                           const float* __restrict__ bc2,
                           float* __restrict__ out) {
    __shared__ float red[LATENT];
    int j = threadIdx.x;
    red[j] = (v[j] + bc1[j]) * Wc2[j];
    __syncthreads();
    for (int s = LATENT / 2; s > 0; s >>= 1) {
        if (j < s) red[j] += red[j + s];
        __syncthreads();
    }
    if (j == 0) out[0] = 1.0f / (1.0f + expf(-(red[0] + bc2[0])));
}

// ---------------- launch ----------------------------------------------------
extern "C" void kernel_launch(void* const* d_in, const int* in_sizes, int n_in,
                              void* d_out, int out_size) {
    const float* z    = (const float*)d_in[0];
    const void*  eidx = d_in[1];
    const float* W1a  = (const float*)d_in[2];
    const float* b1a  = (const float*)d_in[3];
    const float* W1b  = (const float*)d_in[4];
    const float* b1b  = (const float*)d_in[5];
    const float* W2a  = (const float*)d_in[6];
    const float* b2a  = (const float*)d_in[7];
    const float* W2b  = (const float*)d_in[8];
    const float* b2b  = (const float*)d_in[9];
    const float* Wc1  = (const float*)d_in[10];
    const float* bc1  = (const float*)d_in[11];
    const float* Wc2  = (const float*)d_in[12];
    const float* bc2  = (const float*)d_in[13];
    float* out = (float*)d_out;

    float *accA, *accB, *accC, *v;
    cudaGetSymbolAddress((void**)&accA, g_accA);
    cudaGetSymbolAddress((void**)&accB, g_accB);
    cudaGetSymbolAddress((void**)&accC, g_accC);
    cudaGetSymbolAddress((void**)&v,    g_v);

    const int nNT = N_NODES * N_T;   // 77824

    // K0: adjacency + zero accA/accB/accC/v
    init_kernel<<<148, 256>>>(eidx, accA, accB, accC, v);

    // g1a: accA = agg(z) @ W1a          [19,512]x[512,2048]  (64 blocks)
    gemm_fused<32, 0><<<dim3(HID / 512, LATENT / 32), 256>>>(
        z, nullptr, W1a, accA, nullptr, 0, LATENT, HID, 32);

    // g1b: accB = relu(accA+b1a) @ W1b  [19,2048]x[2048,2048] (128 blocks)
    gemm_fused<64, 1><<<dim3(HID / 512, HID / 64), 256>>>(
        accA, b1a, W1b, accB, nullptr, 0, HID, HID, 64);

    // g2a: accC = agg(relu(accB+b1b)) @ W2a  [19,2048]x[2048,4096] (256 blocks)
    //      (also lazily zeroes accA for g2b)
    gemm_fused<64, 2><<<dim3(N_T / 512, HID / 64), 256>>>(
        accB, b1b, W2a, accC, accA, nNT, HID, N_T, 64);

    // g2b: accA = relu(accC+b2a) @ W2b  [19,4096]x[4096,4096] (256 blocks)
    gemm_fused<64, 1><<<dim3(N_T / 512, N_T / 128), 256>>>(
        accC, b2a, W2b, accA, nullptr, 0, N_T, N_T, 128);

    // classifier: epilogue (+b2b, write out[1:]) fused into FC1
    fc1_kernel<<<592, 128>>>(accA, b2b, Wc1, v, out + 1, 132);
    fc2_kernel<<<1, 512>>>(v, bc1, Wc2, bc2, out);
}

// round 7
// speedup vs baseline: 1.8672x; 1.0240x over previous
#include <cuda_runtime.h>
#include <cuda_bf16.h>
#include <math.h>

#define N_NODES 19
#define N_T     4096
#define LATENT  512
#define HID     2048
#define N_EDGES 342

// ---------------- scratch (__device__ globals; no allocs allowed) -----------
__device__ float g_accA[N_NODES * N_T];
__device__ float g_accB[N_NODES * N_T];
__device__ float g_accC[N_NODES * N_T];
__device__ float g_v[LATENT];
__device__ float g_adjf[N_NODES * N_NODES]; // dense edge-count matrix [dst][src]

// ---------------- K0: adjacency + zero all accumulators ---------------------
__global__ void init_kernel(const void* __restrict__ eidx,
                            float* __restrict__ accA,
                            float* __restrict__ accB,
                            float* __restrict__ accC,
                            float* __restrict__ v) {
    int t = threadIdx.x;
    if (blockIdx.x == 0) {
        __shared__ int cnt[N_NODES * N_NODES];
        __shared__ int s_i64;
        for (int i = t; i < N_NODES * N_NODES; i += blockDim.x) cnt[i] = 0;
        if (t == 0) {
            const long long* e64 = (const long long*)eidx;
            int ok = 1;
            for (int i = 0; i < N_EDGES; ++i) {
                long long x = e64[i];
                if (x < 0 || x >= N_NODES) { ok = 0; break; }
            }
            s_i64 = ok;
        }
        __syncthreads();
        const long long* e64 = (const long long*)eidx;
        const int*       e32 = (const int*)eidx;
        for (int e = t; e < N_EDGES; e += blockDim.x) {
            int src, dst;
            if (s_i64) { src = (int)e64[e]; dst = (int)e64[N_EDGES + e]; }
            else       { src = e32[e];      dst = e32[N_EDGES + e]; }
            atomicAdd(&cnt[dst * N_NODES + src], 1);
        }
        __syncthreads();
        for (int i = t; i < N_NODES * N_NODES; i += blockDim.x)
            g_adjf[i] = (float)cnt[i];
        for (int i = t; i < LATENT; i += blockDim.x) v[i] = 0.0f;
    }
    const int n4 = (N_NODES * N_T) >> 2;
    float4 zz = make_float4(0.f, 0.f, 0.f, 0.f);
    for (int q = blockIdx.x * blockDim.x + t; q < n4;
         q += gridDim.x * blockDim.x) {
        reinterpret_cast<float4*>(accA)[q] = zz;
        reinterpret_cast<float4*>(accB)[q] = zz;
        reinterpret_cast<float4*>(accC)[q] = zz;
    }
}

// ---------------- fused split-K GEMM with cp.async W pipeline ---------------
// Cacc += stage(Ain)[19, K] @ W[K, N].  256 threads x 2 cols = 512-col tile.
// Each block owns ONE K-slab of KC rows (grid.y slabs).
// W is streamed through an S-stage cp.async ring (stage = 8 k-rows x 512 cols
// = 16 KB), giving (S-1)*16KB of DRAM traffic in flight per block with zero
// register cost. A slab is staged once (fused agg/bias/relu) as duplicated
// {a,a} pairs for fma.rn.f32x2.
// MODE 0: stage = agg(Ain); 1: relu(Ain+bias); 2: agg(relu(Ain+bias)).
template<int KC, int MODE, int S>
__global__ __launch_bounds__(256, 2) void gemm_pipe(
        const float* __restrict__ Ain, const float* __restrict__ bias,
        const float* __restrict__ W, float* __restrict__ Cacc,
        float* __restrict__ zbuf, int zn, int K, int N) {
    extern __shared__ __align__(16) char dsm[];
    float* sW = (float*)dsm;                                    // S*8*512 floats
    unsigned long long* sA =
        (unsigned long long*)(dsm + (size_t)S * 8 * 512 * 4);   // [19][KC]
    float* sRaw = (float*)(sA + N_NODES * KC);                  // [19][KC] (MODE!=1)
    __shared__ float s_adj[N_NODES * N_NODES];

    const int tid = threadIdx.x;
    const int colbase = blockIdx.x * 512;
    const int kbeg = blockIdx.y * KC;

    // lazy zeroing for a future accumulator
    if (zbuf) {
        int n4 = zn >> 2;
        float4 zz = make_float4(0.f, 0.f, 0.f, 0.f);
        for (int q = (blockIdx.y * gridDim.x + blockIdx.x) * 256 + tid;
             q < n4; q += gridDim.x * gridDim.y * 256)
            reinterpret_cast<float4*>(zbuf)[q] = zz;
    }
    if (MODE != 1) {
        for (int i = tid; i < N_NODES * N_NODES; i += 256)
            s_adj[i] = g_adjf[i];
    }

    // ---- stage A slab (fused epilogue/agg), duplicated pairs ----
    for (int i = tid; i < N_NODES * KC; i += 256) {
        int r = i / KC, k = i - r * KC;
        float a = Ain[r * K + kbeg + k];
        if (MODE >= 1) a = fmaxf(a + bias[kbeg + k], 0.0f);
        if (MODE == 1) {
            unsigned long long p;
            asm("mov.b64 %0, {%1, %1};" : "=l"(p) : "f"(a));
            sA[i] = p;
        } else {
            sRaw[i] = a;
        }
    }
    __syncthreads();
    if (MODE != 1) {
        for (int i = tid; i < N_NODES * KC; i += 256) {
            int r = i / KC, k = i - r * KC;
            float a = sRaw[r * KC + k];
#pragma unroll
            for (int s = 0; s < N_NODES; ++s)
                a += s_adj[r * N_NODES + s] * sRaw[s * KC + k];
            unsigned long long p;
            asm("mov.b64 %0, {%1, %1};" : "=l"(p) : "f"(a));
            sA[i] = p;
        }
        __syncthreads();
    }

    constexpr int NST = KC / 8;   // 8-k stages in this slab

    // issue one stage's cp.async loads (16 KB; 4 x 16B per thread)
    auto issue_stage = [&](int s) {
        const float* gsrc = W + (size_t)(kbeg + s * 8) * N + colbase;
        float* dst = sW + (s % S) * 4096;
#pragma unroll
        for (int j = 0; j < 4; ++j) {
            int id  = tid + j * 256;          // 0..1023
            int row = id >> 7;                // 8 rows
            int cp  = (id & 127) << 2;        // 128 x 4-col chunks
            unsigned sm =
                (unsigned)__cvta_generic_to_shared(dst + row * 512 + cp);
            const float* g = gsrc + (size_t)row * N + cp;
            asm volatile("cp.async.cg.shared.global [%0], [%1], 16;\n"
                         :: "r"(sm), "l"(g));
        }
    };

    unsigned long long acc[N_NODES];
#pragma unroll
    for (int r = 0; r < N_NODES; ++r) acc[r] = 0ull;

    // prologue: fill S-1 stages
#pragma unroll
    for (int s = 0; s < S - 1; ++s) {
        if (s < NST) issue_stage(s);
        asm volatile("cp.async.commit_group;\n");
    }

#pragma unroll 1
    for (int t = 0; t < NST; ++t) {
        asm volatile("cp.async.wait_group %0;\n" :: "n"(S - 2));
        __syncthreads();   // all threads' stage-t data arrived; buffer (t-1)%S free

        const float* wb = sW + (t % S) * 4096;
#pragma unroll
        for (int kk = 0; kk < 8; kk += 2) {
            unsigned long long w0 = *reinterpret_cast<const unsigned long long*>(
                                        wb + kk * 512 + 2 * tid);
            unsigned long long w1 = *reinterpret_cast<const unsigned long long*>(
                                        wb + (kk + 1) * 512 + 2 * tid);
#pragma unroll
            for (int r = 0; r < N_NODES; ++r) {
                ulonglong2 a2 = *reinterpret_cast<const ulonglong2*>(
                                    sA + r * KC + t * 8 + kk);
                asm("fma.rn.f32x2 %0, %1, %2, %0;"
                    : "+l"(acc[r]) : "l"(a2.x), "l"(w0));
                asm("fma.rn.f32x2 %0, %1, %2, %0;"
                    : "+l"(acc[r]) : "l"(a2.y), "l"(w1));
            }
        }
        if (t + S - 1 < NST) issue_stage(t + S - 1);
        asm volatile("cp.async.commit_group;\n");
    }

    const int col = colbase + tid * 2;
#pragma unroll
    for (int r = 0; r < N_NODES; ++r) {
        float2 p = *reinterpret_cast<float2*>(&acc[r]);
        atomicAdd(&Cacc[r * N + col],     p.x);
        atomicAdd(&Cacc[r * N + col + 1], p.y);
    }
}

// ---------------- FC1 fused: flat = acc + b2b (also written to out1);
//                  v[512] += flat @ Wc1 --------------------------------------
__global__ __launch_bounds__(128) void fc1_kernel(
        const float* __restrict__ acc, const float* __restrict__ b2b,
        const float* __restrict__ Wc1, float* __restrict__ v,
        float* __restrict__ out1, int rows_per) {
    const int ROWS = N_NODES * N_T;
    int t = threadIdx.x;                       // cols 4t..4t+3
    int r0 = blockIdx.x * rows_per;
    int r1 = min(r0 + rows_per, ROWS);
    float4 s = make_float4(0.f, 0.f, 0.f, 0.f);
    int i = r0;
    for (; i + 8 <= r1; i += 8) {
        float f[8];
        float4 w[8];
#pragma unroll
        for (int u = 0; u < 8; ++u) {
            f[u] = acc[i + u] + b2b[(i + u) & (N_T - 1)];
            w[u] = *reinterpret_cast<const float4*>(
                       &Wc1[(size_t)(i + u) * LATENT + 4 * t]);
        }
#pragma unroll
        for (int u = 0; u < 8; ++u) {
            if (t == ((i + u) & 127)) out1[i + u] = f[u];
            s.x += f[u] * w[u].x; s.y += f[u] * w[u].y;
            s.z += f[u] * w[u].z; s.w += f[u] * w[u].w;
        }
    }
    for (; i < r1; ++i) {
        float f = acc[i] + b2b[i & (N_T - 1)];
        if (t == (i & 127)) out1[i] = f;
        float4 w = *reinterpret_cast<const float4*>(
                       &Wc1[(size_t)i * LATENT + 4 * t]);
        s.x += f * w.x; s.y += f * w.y; s.z += f * w.z; s.w += f * w.w;
    }
    atomicAdd(&v[4 * t],     s.x);
    atomicAdd(&v[4 * t + 1], s.y);
    atomicAdd(&v[4 * t + 2], s.z);
    atomicAdd(&v[4 * t + 3], s.w);
}

// ---------------- FC2 + sigmoid ---------------------------------------------
__global__ void fc2_kernel(const float* __restrict__ v,
                           const float* __restrict__ bc1,
                           const float* __restrict__ Wc2,
                           const float* __restrict__ bc2,
                           float* __restrict__ out) {
    __shared__ float red[LATENT];
    int j = threadIdx.x;
    red[j] = (v[j] + bc1[j]) * Wc2[j];
    __syncthreads();
    for (int s = LATENT / 2; s > 0; s >>= 1) {
        if (j < s) red[j] += red[j + s];
        __syncthreads();
    }
    if (j == 0) out[0] = 1.0f / (1.0f + expf(-(red[0] + bc2[0])));
}

// ---------------- launch ----------------------------------------------------
#define PIPE_S 5
static inline int pipe_smem(int kc, int mode) {
    return PIPE_S * 8 * 512 * 4 + kc * N_NODES * 8 +
           (mode != 1 ? kc * N_NODES * 4 : 0);
}

extern "C" void kernel_launch(void* const* d_in, const int* in_sizes, int n_in,
                              void* d_out, int out_size) {
    const float* z    = (const float*)d_in[0];
    const void*  eidx = d_in[1];
    const float* W1a  = (const float*)d_in[2];
    const float* b1a  = (const float*)d_in[3];
    const float* W1b  = (const float*)d_in[4];
    const float* b1b  = (const float*)d_in[5];
    const float* W2a  = (const float*)d_in[6];
    const float* b2a  = (const float*)d_in[7];
    const float* W2b  = (const float*)d_in[8];
    const float* b2b  = (const float*)d_in[9];
    const float* Wc1  = (const float*)d_in[10];
    const float* bc1  = (const float*)d_in[11];
    const float* Wc2  = (const float*)d_in[12];
    const float* bc2  = (const float*)d_in[13];
    float* out = (float*)d_out;

    float *accA, *accB, *accC, *v;
    cudaGetSymbolAddress((void**)&accA, g_accA);
    cudaGetSymbolAddress((void**)&accB, g_accB);
    cudaGetSymbolAddress((void**)&accC, g_accC);
    cudaGetSymbolAddress((void**)&v,    g_v);

    const int nNT = N_NODES * N_T;   // 77824

    // opt-in to >48KB dynamic smem (idempotent; host-state only)
    static int attr_done = 0;
    if (!attr_done) {
        cudaFuncSetAttribute(gemm_pipe<32, 0, PIPE_S>,
            cudaFuncAttributeMaxDynamicSharedMemorySize, pipe_smem(32, 0));
        cudaFuncSetAttribute(gemm_pipe<64, 1, PIPE_S>,
            cudaFuncAttributeMaxDynamicSharedMemorySize, pipe_smem(64, 1));
        cudaFuncSetAttribute(gemm_pipe<64, 2, PIPE_S>,
            cudaFuncAttributeMaxDynamicSharedMemorySize, pipe_smem(64, 2));
        cudaFuncSetAttribute(gemm_pipe<128, 1, PIPE_S>,
            cudaFuncAttributeMaxDynamicSharedMemorySize, pipe_smem(128, 1));
        attr_done = 1;
    }

    // K0: adjacency + zero accA/accB/accC/v
    init_kernel<<<148, 256>>>(eidx, accA, accB, accC, v);

    // g1a: accA = agg(z) @ W1a          [19,512]x[512,2048]
    gemm_pipe<32, 0, PIPE_S><<<dim3(HID / 512, LATENT / 32), 256,
                               pipe_smem(32, 0)>>>(
        z, nullptr, W1a, accA, nullptr, 0, LATENT, HID);

    // g1b: accB = relu(accA+b1a) @ W1b  [19,2048]x[2048,2048]
    gemm_pipe<64, 1, PIPE_S><<<dim3(HID / 512, HID / 64), 256,
                               pipe_smem(64, 1)>>>(
        accA, b1a, W1b, accB, nullptr, 0, HID, HID);

    // g2a: accC = agg(relu(accB+b1b)) @ W2a  [19,2048]x[2048,4096]
    //      (also lazily zeroes accA for g2b)
    gemm_pipe<64, 2, PIPE_S><<<dim3(N_T / 512, HID / 64), 256,
                               pipe_smem(64, 2)>>>(
        accB, b1b, W2a, accC, accA, nNT, HID, N_T);

    // g2b: accA = relu(accC+b2a) @ W2b  [19,4096]x[4096,4096]
    gemm_pipe<128, 1, PIPE_S><<<dim3(N_T / 512, N_T / 128), 256,
                                pipe_smem(128, 1)>>>(
        accC, b2a, W2b, accA, nullptr, 0, N_T, N_T);

    // classifier: epilogue (+b2b, write out[1:]) fused into FC1
    fc1_kernel<<<592, 128>>>(accA, b2b, Wc1, v, out + 1, 132);
    fc2_kernel<<<1, 512>>>(v, bc1, Wc2, bc2, out);
}